// round 4
// baseline (speedup 1.0000x reference)
#include <cuda_runtime.h>
#include <cuda_bf16.h>
#include <cstdint>

#define TOKENS 8192
#define IN_F   4096
#define OUT_F  4096

// ---------------------------------------------------------------------------
// Scratch (__device__ globals; alloc-free rule)
// ---------------------------------------------------------------------------
__device__ int8_t  g_qhi[(size_t)TOKENS * IN_F];   // x16 >> 8   (s8)
__device__ uint8_t g_qlo[(size_t)TOKENS * IN_F];   // x16 & 255  (u8)
__device__ int8_t  g_w8 [(size_t)OUT_F  * IN_F];   // packed int8 weights
__device__ float   g_xs [TOKENS];                  // per-row scale s16

__device__ int g_w_is_i32;   // weights delivered as int32 words vs packed int8
__device__ int g_sb_swap;    // d_in[2]/d_in[3] order (scales vs bias)

// ---------------------------------------------------------------------------
// Input-interpretation detector (data-driven, deterministic)
// ---------------------------------------------------------------------------
__global__ void detect_kernel(const int* __restrict__ wbuf,
                              const float* __restrict__ maybe_scales) {
    if (threadIdx.x == 0 && blockIdx.x == 0) {
        int ok = 1;
        for (int i = 0; i < 64; i++) {
            int v = wbuf[i];
            if (v < -128 || v > 127) ok = 0;
        }
        g_w_is_i32 = ok;
        int plausible = 1;
        for (int i = 0; i < 64; i++) {
            float s = maybe_scales[i];
            if (!(s > 0.0f && s < 0.5f)) plausible = 0;
        }
        g_sb_swap = plausible ? 0 : 1;
    }
}

// ---------------------------------------------------------------------------
// x quantization: per-row int16 levels, split into s8 hi / u8 lo.
//   x ~= s16 * (256*hi + lo),  s16 = rowmax/32000  -> residual <= s16/2
// ---------------------------------------------------------------------------
__global__ __launch_bounds__(128) void quantize_x_kernel(const float* __restrict__ x) {
    const int row = blockIdx.x;
    const int tid = threadIdx.x;
    const float4* xr = reinterpret_cast<const float4*>(x + (size_t)row * IN_F);

    float4 v[8];
    float m = 0.f;
#pragma unroll
    for (int j = 0; j < 8; j++) {
        v[j] = xr[tid + j * 128];
        m = fmaxf(m, fmaxf(fmaxf(fabsf(v[j].x), fabsf(v[j].y)),
                           fmaxf(fabsf(v[j].z), fabsf(v[j].w))));
    }
    __shared__ float red[128];
    red[tid] = m;
    __syncthreads();
#pragma unroll
    for (int s = 64; s > 0; s >>= 1) {
        if (tid < s) red[tid] = fmaxf(red[tid], red[tid + s]);
        __syncthreads();
    }
    float ma  = red[0];
    float s16 = (ma > 0.f) ? ma / 32000.f : 1.f;
    float inv = 1.f / s16;
    if (tid == 0) g_xs[row] = s16;

    char4*  qh = reinterpret_cast<char4*>(g_qhi + (size_t)row * IN_F);
    uchar4* ql = reinterpret_cast<uchar4*>(g_qlo + (size_t)row * IN_F);
#pragma unroll
    for (int j = 0; j < 8; j++) {
        float vv[4] = {v[j].x, v[j].y, v[j].z, v[j].w};
        int hi[4]; unsigned lo[4];
#pragma unroll
        for (int q = 0; q < 4; q++) {
            int xi = __float2int_rn(vv[q] * inv);
            hi[q] = xi >> 8;                // arithmetic shift
            lo[q] = (unsigned)xi & 255u;
        }
        qh[tid + j * 128] = make_char4((char)hi[0], (char)hi[1], (char)hi[2], (char)hi[3]);
        ql[tid + j * 128] = make_uchar4((unsigned char)lo[0], (unsigned char)lo[1],
                                        (unsigned char)lo[2], (unsigned char)lo[3]);
    }
}

// W: int32 words -> packed int8 (or passthrough copy if already packed)
__global__ void convert_w_kernel(const void* __restrict__ w) {
    size_t i = (size_t)blockIdx.x * blockDim.x + threadIdx.x;   // per 4 int8
    char4 o;
    if (g_w_is_i32) {
        int4 c = reinterpret_cast<const int4*>(w)[i];
        o = make_char4((char)c.x, (char)c.y, (char)c.z, (char)c.w);
    } else {
        o = reinterpret_cast<const char4*>(w)[i];
    }
    reinterpret_cast<char4*>(g_w8)[i] = o;
}

// ---------------------------------------------------------------------------
// Int8 IMMA GEMM: CTA 128x128, 16 warps (4x4, warp tile 32x32),
//   BK=128 per stage, 3-stage cp.async pipeline.
//   Per k32 step: 8 s8 MMAs (hi) + 8 u8 MMAs (lo) per warp, int32 accum.
// ---------------------------------------------------------------------------
constexpr int BM = 128, BN = 128, BK = 128;
constexpr int STAGES = 3;
constexpr int ROWB = BK + 16;                      // 144 B: conflict-free ldsm
constexpr int A_BYTES = BM * ROWB;                 // 18432
constexpr int STAGE_BYTES = 3 * A_BYTES;           // hi + lo + W = 55296
constexpr int SMEM_BYTES = STAGES * STAGE_BYTES;   // 165888

__device__ __forceinline__ uint32_t smem_u32(const void* p) {
    return (uint32_t)__cvta_generic_to_shared(p);
}
__device__ __forceinline__ void cp16(uint32_t dst, const void* src) {
    asm volatile("cp.async.cg.shared.global [%0], [%1], 16;\n" :: "r"(dst), "l"(src));
}
__device__ __forceinline__ void ldsm_x4(uint32_t r[4], uint32_t addr) {
    asm volatile("ldmatrix.sync.aligned.m8n8.x4.shared.b16 {%0,%1,%2,%3}, [%4];\n"
                 : "=r"(r[0]), "=r"(r[1]), "=r"(r[2]), "=r"(r[3]) : "r"(addr));
}
__device__ __forceinline__ void imma_s8(int c[4], const uint32_t a[4],
                                        uint32_t b0, uint32_t b1) {
    asm volatile(
        "mma.sync.aligned.m16n8k32.row.col.s32.s8.s8.s32 "
        "{%0,%1,%2,%3}, {%4,%5,%6,%7}, {%8,%9}, {%0,%1,%2,%3};\n"
        : "+r"(c[0]), "+r"(c[1]), "+r"(c[2]), "+r"(c[3])
        : "r"(a[0]), "r"(a[1]), "r"(a[2]), "r"(a[3]), "r"(b0), "r"(b1));
}
__device__ __forceinline__ void imma_u8(int c[4], const uint32_t a[4],
                                        uint32_t b0, uint32_t b1) {
    asm volatile(
        "mma.sync.aligned.m16n8k32.row.col.s32.u8.s8.s32 "
        "{%0,%1,%2,%3}, {%4,%5,%6,%7}, {%8,%9}, {%0,%1,%2,%3};\n"
        : "+r"(c[0]), "+r"(c[1]), "+r"(c[2]), "+r"(c[3])
        : "r"(a[0]), "r"(a[1]), "r"(a[2]), "r"(a[3]), "r"(b0), "r"(b1));
}

__device__ __forceinline__ void load_stage(int tid, uint32_t stage_u32,
    const int8_t* gH, const uint8_t* gL, const int8_t* gW, int k0) {
#pragma unroll
    for (int i = 0; i < 6; i++) {
        int cid = tid + i * 512;     // 3072 16B-chunks: 384 rows x 8
        int r   = cid >> 3;
        int c   = cid & 7;
        int region = (r >= 256) ? 2 : (r >= 128) ? 1 : 0;
        int rr = r - region * 128;
        const void* src =
            (region == 0) ? (const void*)(gH + (size_t)rr * IN_F + k0 + c * 16) :
            (region == 1) ? (const void*)(gL + (size_t)rr * IN_F + k0 + c * 16) :
                            (const void*)(gW + (size_t)rr * IN_F + k0 + c * 16);
        cp16(stage_u32 + region * A_BYTES + rr * ROWB + c * 16, src);
    }
}

__global__ __launch_bounds__(512, 1)
void gemm_i8_kernel(const float* __restrict__ p2, const float* __restrict__ p3,
                    float* __restrict__ out) {
    const float* scales = g_sb_swap ? p3 : p2;
    const float* bias   = g_sb_swap ? p2 : p3;

    extern __shared__ char smem[];
    const int tid = threadIdx.x;
    const int wid = tid >> 5, l = tid & 31;
    const int wm = wid >> 2, wn = wid & 3;        // 4x4 warps, 32x32 tiles
    const int bn0 = blockIdx.x * BN;
    const int bm0 = blockIdx.y * BM;

    const int8_t*  gH = g_qhi + (size_t)bm0 * IN_F;
    const uint8_t* gL = g_qlo + (size_t)bm0 * IN_F;
    const int8_t*  gW = g_w8  + (size_t)bn0 * IN_F;

    const uint32_t sbase = smem_u32(smem);

    int accH[2][4][4], accL[2][4][4];
#pragma unroll
    for (int a = 0; a < 2; a++)
#pragma unroll
        for (int b = 0; b < 4; b++)
#pragma unroll
            for (int c = 0; c < 4; c++) { accH[a][b][c] = 0; accL[a][b][c] = 0; }

    // ldmatrix lane addressing (byte offsets; b16 view of int8 rows)
    const int mRow = wm * 32 + (l & 7) + ((l >> 3) & 1) * 8;   // + mt*16
    const int nRow = wn * 32 + (l & 7) + ((l >> 3) & 1) * 8;   // + p*16
    const int kOff = ((l >> 4) & 1) * 16;                      // + ks*32

    const int KT = IN_F / BK;   // 32

#pragma unroll
    for (int s = 0; s < STAGES - 1; s++) {
        load_stage(tid, sbase + s * STAGE_BYTES, gH, gL, gW, s * BK);
        asm volatile("cp.async.commit_group;" ::: "memory");
    }
    asm volatile("cp.async.wait_group %0;" :: "n"(STAGES - 2) : "memory");
    __syncthreads();

    for (int kt = 0; kt < KT; kt++) {
        int nkt = kt + STAGES - 1;
        if (nkt < KT)
            load_stage(tid, sbase + (nkt % STAGES) * STAGE_BYTES, gH, gL, gW, nkt * BK);
        asm volatile("cp.async.commit_group;" ::: "memory");

        uint32_t st = sbase + (kt % STAGES) * STAGE_BYTES;
#pragma unroll
        for (int ks = 0; ks < 4; ks++) {           // 4 x k32 per stage
            uint32_t bfr[2][4];
#pragma unroll
            for (int p = 0; p < 2; p++)
                ldsm_x4(bfr[p], st + 2 * A_BYTES + (nRow + p * 16) * ROWB + ks * 32 + kOff);

            uint32_t a[2][4];
#pragma unroll
            for (int mt = 0; mt < 2; mt++)
                ldsm_x4(a[mt], st + (mRow + mt * 16) * ROWB + ks * 32 + kOff);
#pragma unroll
            for (int mt = 0; mt < 2; mt++)
#pragma unroll
                for (int nt = 0; nt < 4; nt++)
                    imma_s8(accH[mt][nt], a[mt],
                            bfr[nt >> 1][nt & 1], bfr[nt >> 1][(nt & 1) + 2]);
#pragma unroll
            for (int mt = 0; mt < 2; mt++)
                ldsm_x4(a[mt], st + A_BYTES + (mRow + mt * 16) * ROWB + ks * 32 + kOff);
#pragma unroll
            for (int mt = 0; mt < 2; mt++)
#pragma unroll
                for (int nt = 0; nt < 4; nt++)
                    imma_u8(accL[mt][nt], a[mt],
                            bfr[nt >> 1][nt & 1], bfr[nt >> 1][(nt & 1) + 2]);
        }

        asm volatile("cp.async.wait_group %0;" :: "n"(STAGES - 2) : "memory");
        __syncthreads();
    }

    // Epilogue: y = s16[m] * (256*hi + lo) * scales[n] + bias[n]
#pragma unroll
    for (int mt = 0; mt < 2; mt++) {
        int r0 = bm0 + wm * 32 + mt * 16 + (l >> 2);
        float sx0 = g_xs[r0], sx1 = g_xs[r0 + 8];
#pragma unroll
        for (int nt = 0; nt < 4; nt++) {
            int gn = bn0 + wn * 32 + nt * 8 + (l & 3) * 2;
            float sc0 = scales[gn], sc1 = scales[gn + 1];
            float bb0 = bias[gn],   bb1 = bias[gn + 1];
            float v0 = fmaf(256.f, (float)accH[mt][nt][0], (float)accL[mt][nt][0]) * sx0;
            float v1 = fmaf(256.f, (float)accH[mt][nt][1], (float)accL[mt][nt][1]) * sx0;
            float v2 = fmaf(256.f, (float)accH[mt][nt][2], (float)accL[mt][nt][2]) * sx1;
            float v3 = fmaf(256.f, (float)accH[mt][nt][3], (float)accL[mt][nt][3]) * sx1;
            *reinterpret_cast<float2*>(out + (size_t)r0 * OUT_F + gn) =
                make_float2(fmaf(v0, sc0, bb0), fmaf(v1, sc1, bb1));
            *reinterpret_cast<float2*>(out + (size_t)(r0 + 8) * OUT_F + gn) =
                make_float2(fmaf(v2, sc0, bb0), fmaf(v3, sc1, bb1));
        }
    }
}

// ---------------------------------------------------------------------------
// Launch
// ---------------------------------------------------------------------------
extern "C" void kernel_launch(void* const* d_in, const int* in_sizes, int n_in,
                              void* d_out, int out_size) {
    const float* x   = (const float*)d_in[0];
    const void*  w8  = d_in[1];
    const float* p2  = (const float*)d_in[2];
    const float* p3  = (const float*)d_in[3];
    float*       out = (float*)d_out;

    detect_kernel<<<1, 32>>>((const int*)w8, p2);
    quantize_x_kernel<<<TOKENS, 128>>>(x);
    convert_w_kernel<<<((size_t)OUT_F * IN_F) / 4 / 256, 256>>>(w8);

    cudaFuncSetAttribute(gemm_i8_kernel,
                         cudaFuncAttributeMaxDynamicSharedMemorySize, SMEM_BYTES);
    dim3 grid(OUT_F / BN, TOKENS / BM);   // (32, 64)
    gemm_i8_kernel<<<grid, 512, SMEM_BYTES>>>(p2, p3, out);
}

// round 5
// speedup vs baseline: 5.0016x; 5.0016x over previous
#include <cuda_runtime.h>
#include <cuda_fp16.h>
#include <cstdint>

#define TOKENS 8192
#define IN_F   4096
#define OUT_F  4096

// ---------------------------------------------------------------------------
// Scratch (__device__ globals; alloc-free rule)
// ---------------------------------------------------------------------------
__device__ __half g_xh[(size_t)TOKENS * IN_F];   // x in fp16 (single pass)
__device__ __half g_wh[(size_t)OUT_F  * IN_F];   // int8 weights, exact in fp16

__device__ int g_w_is_i32;   // weights delivered as int32 words vs packed int8
__device__ int g_sb_swap;    // d_in[2]/d_in[3] order (scales vs bias)

// ---------------------------------------------------------------------------
// Input-interpretation detector (data-driven, deterministic)
// ---------------------------------------------------------------------------
__global__ void detect_kernel(const int* __restrict__ wbuf,
                              const float* __restrict__ maybe_scales) {
    if (threadIdx.x == 0 && blockIdx.x == 0) {
        int ok = 1;
        for (int i = 0; i < 64; i++) {
            int v = wbuf[i];
            if (v < -128 || v > 127) ok = 0;
        }
        g_w_is_i32 = ok;
        int plausible = 1;
        for (int i = 0; i < 64; i++) {
            float s = maybe_scales[i];
            if (!(s > 0.0f && s < 0.5f)) plausible = 0;
        }
        g_sb_swap = plausible ? 0 : 1;
    }
}

// ---------------------------------------------------------------------------
// Conversions: x -> fp16 (u=2^-11 rounding), W -> fp16 (exact, |w|<=127)
// ---------------------------------------------------------------------------
__global__ void convert_x_kernel(const float* __restrict__ x) {
    size_t i = (size_t)blockIdx.x * blockDim.x + threadIdx.x;  // per 4 floats
    float4 v = reinterpret_cast<const float4*>(x)[i];
    __half2* p = reinterpret_cast<__half2*>(g_xh);
    p[2 * i + 0] = __floats2half2_rn(v.x, v.y);
    p[2 * i + 1] = __floats2half2_rn(v.z, v.w);
}

__global__ void convert_w_kernel(const void* __restrict__ w) {
    size_t i = (size_t)blockIdx.x * blockDim.x + threadIdx.x;  // per 4 weights
    float f0, f1, f2, f3;
    if (g_w_is_i32) {
        int4 c = reinterpret_cast<const int4*>(w)[i];
        f0 = (float)c.x; f1 = (float)c.y; f2 = (float)c.z; f3 = (float)c.w;
    } else {
        char4 c = reinterpret_cast<const char4*>(w)[i];
        f0 = (float)c.x; f1 = (float)c.y; f2 = (float)c.z; f3 = (float)c.w;
    }
    __half2* p = reinterpret_cast<__half2*>(g_wh);
    p[2 * i + 0] = __floats2half2_rn(f0, f1);
    p[2 * i + 1] = __floats2half2_rn(f2, f3);
}

// ---------------------------------------------------------------------------
// Single-pass fp16 GEMM: C = X@W^T, epilogue *scales[n] + bias[n].
//   CTA 128x128, BK=64, 3-stage cp.async, 8 warps (4x2), warp tile 32x64,
//   mma.sync.m16n8k16.f32.f16.f16.f32.
// ---------------------------------------------------------------------------
constexpr int BM = 128, BN = 128, BK = 64;
constexpr int STAGES = 3;
constexpr int LDS = BK + 8;                        // 72 elems: conflict-free ldsm
constexpr int STAGE_ELEMS = (BM + BN) * LDS;       // 18432 elems
constexpr int SMEM_BYTES = STAGES * STAGE_ELEMS * 2;  // 110592 B (2 CTAs/SM)

__device__ __forceinline__ uint32_t smem_u32(const void* p) {
    return (uint32_t)__cvta_generic_to_shared(p);
}
__device__ __forceinline__ void cp16(uint32_t dst, const void* src) {
    asm volatile("cp.async.cg.shared.global [%0], [%1], 16;\n" :: "r"(dst), "l"(src));
}
__device__ __forceinline__ void ldsm_x4(uint32_t r[4], uint32_t addr) {
    asm volatile("ldmatrix.sync.aligned.m8n8.x4.shared.b16 {%0,%1,%2,%3}, [%4];\n"
                 : "=r"(r[0]), "=r"(r[1]), "=r"(r[2]), "=r"(r[3]) : "r"(addr));
}
__device__ __forceinline__ void mma16816(float c[4], const uint32_t a[4],
                                         uint32_t b0, uint32_t b1) {
    asm volatile(
        "mma.sync.aligned.m16n8k16.row.col.f32.f16.f16.f32 "
        "{%0,%1,%2,%3}, {%4,%5,%6,%7}, {%8,%9}, {%0,%1,%2,%3};\n"
        : "+f"(c[0]), "+f"(c[1]), "+f"(c[2]), "+f"(c[3])
        : "r"(a[0]), "r"(a[1]), "r"(a[2]), "r"(a[3]), "r"(b0), "r"(b1));
}

__device__ __forceinline__ void load_stage(
    int tid, __half* s, const __half* gA, const __half* gB, int k0) {
    __half* sA = s;
    __half* sB = s + BM * LDS;
#pragma unroll
    for (int i = 0; i < 4; i++) {
        int cid  = tid + i * 256;     // 1024 chunks for A, interleaved with B below
        int row  = cid >> 3;          // 0..127
        int col8 = (cid & 7) * 8;     // 8 chunks of 8 halves per 64-elem row
        cp16(smem_u32(sA + row * LDS + col8), gA + (size_t)row * IN_F + k0 + col8);
        cp16(smem_u32(sB + row * LDS + col8), gB + (size_t)row * IN_F + k0 + col8);
    }
}

__global__ __launch_bounds__(256, 2)
void gemm_kernel(const float* __restrict__ p2, const float* __restrict__ p3,
                 float* __restrict__ out) {
    const float* scales = g_sb_swap ? p3 : p2;
    const float* bias   = g_sb_swap ? p2 : p3;

    extern __shared__ __half smem[];
    const int tid = threadIdx.x;
    const int bm0 = blockIdx.y * BM;
    const int bn0 = blockIdx.x * BN;

    const __half* gA = g_xh + (size_t)bm0 * IN_F;
    const __half* gB = g_wh + (size_t)bn0 * IN_F;

    const int w  = tid >> 5, l = tid & 31;
    const int wm = w >> 1,  wn = w & 1;   // 4x2 warp grid; warp tile 32x64

    float acc[2][8][4];
#pragma unroll
    for (int a = 0; a < 2; a++)
#pragma unroll
        for (int b = 0; b < 8; b++)
#pragma unroll
            for (int c = 0; c < 4; c++) acc[a][b][c] = 0.f;

    // ldmatrix per-lane addressing (element offsets within a tile)
    const int aRow = wm * 32 + (l & 7) + ((l >> 3) & 1) * 8;  // + mt*16
    const int aCol = (l >> 4) * 8;                            // + ks*16
    const int bRow = wn * 64 + (l >> 4) * 8 + (l & 7);        // + q*16
    const int bCol = ((l >> 3) & 1) * 8;                      // + ks*16

    const int KT = IN_F / BK;  // 64

#pragma unroll
    for (int s = 0; s < STAGES - 1; s++) {
        load_stage(tid, smem + s * STAGE_ELEMS, gA, gB, s * BK);
        asm volatile("cp.async.commit_group;\n" ::: "memory");
    }
    asm volatile("cp.async.wait_group %0;\n" :: "n"(STAGES - 2) : "memory");
    __syncthreads();

    for (int kt = 0; kt < KT; kt++) {
        int nkt = kt + STAGES - 1;
        if (nkt < KT)
            load_stage(tid, smem + (nkt % STAGES) * STAGE_ELEMS, gA, gB, nkt * BK);
        asm volatile("cp.async.commit_group;\n" ::: "memory");

        __half* s  = smem + (kt % STAGES) * STAGE_ELEMS;
        __half* sA = s;
        __half* sB = s + BM * LDS;

#pragma unroll
        for (int ks = 0; ks < 4; ks++) {          // 4 x k16 per BK=64 stage
            uint32_t bfr[4][4];
#pragma unroll
            for (int q = 0; q < 4; q++)
                ldsm_x4(bfr[q], smem_u32(sB + (bRow + q * 16) * LDS + bCol + ks * 16));
            uint32_t a[2][4];
#pragma unroll
            for (int mt = 0; mt < 2; mt++)
                ldsm_x4(a[mt], smem_u32(sA + (aRow + mt * 16) * LDS + aCol + ks * 16));
#pragma unroll
            for (int mt = 0; mt < 2; mt++)
#pragma unroll
                for (int nt = 0; nt < 8; nt++)
                    mma16816(acc[mt][nt], a[mt],
                             bfr[nt >> 1][(nt & 1) * 2], bfr[nt >> 1][(nt & 1) * 2 + 1]);
        }

        asm volatile("cp.async.wait_group %0;\n" :: "n"(STAGES - 2) : "memory");
        __syncthreads();
    }

    // Epilogue: y = acc * scales[n] + bias[n]
    const int mbase = bm0 + wm * 32;
    const int nbase = bn0 + wn * 64;
#pragma unroll
    for (int nt = 0; nt < 8; nt++) {
        int gn = nbase + nt * 8 + (l & 3) * 2;
        float s0 = scales[gn],     s1 = scales[gn + 1];
        float b0 = bias[gn],       b1 = bias[gn + 1];
#pragma unroll
        for (int mt = 0; mt < 2; mt++) {
            int gm = mbase + mt * 16 + (l >> 2);
            float2 v0 = make_float2(fmaf(acc[mt][nt][0], s0, b0),
                                    fmaf(acc[mt][nt][1], s1, b1));
            float2 v1 = make_float2(fmaf(acc[mt][nt][2], s0, b0),
                                    fmaf(acc[mt][nt][3], s1, b1));
            *reinterpret_cast<float2*>(out + (size_t)gm * OUT_F + gn)       = v0;
            *reinterpret_cast<float2*>(out + (size_t)(gm + 8) * OUT_F + gn) = v1;
        }
    }
}

// ---------------------------------------------------------------------------
// Launch
// ---------------------------------------------------------------------------
extern "C" void kernel_launch(void* const* d_in, const int* in_sizes, int n_in,
                              void* d_out, int out_size) {
    const float* x   = (const float*)d_in[0];
    const void*  w8  = d_in[1];
    const float* p2  = (const float*)d_in[2];
    const float* p3  = (const float*)d_in[3];
    float*       out = (float*)d_out;

    detect_kernel<<<1, 32>>>((const int*)w8, p2);
    convert_x_kernel<<<((size_t)TOKENS * IN_F) / 4 / 256, 256>>>(x);
    convert_w_kernel<<<((size_t)OUT_F  * IN_F) / 4 / 256, 256>>>(w8);

    cudaFuncSetAttribute(gemm_kernel,
                         cudaFuncAttributeMaxDynamicSharedMemorySize, SMEM_BYTES);
    dim3 grid(OUT_F / BN, TOKENS / BM);   // (32, 64): x fast -> B reuse in L2
    gemm_kernel<<<grid, 256, SMEM_BYTES>>>(p2, p3, out);
}

// round 7
// speedup vs baseline: 5.2115x; 1.0420x over previous
#include <cuda_runtime.h>
#include <cuda_fp16.h>
#include <cstdint>

#define TOKENS 8192
#define IN_F   4096
#define OUT_F  4096

// ---------------------------------------------------------------------------
// Scratch (__device__ globals; alloc-free rule)
// ---------------------------------------------------------------------------
__device__ __half g_xh[(size_t)TOKENS * IN_F];   // x in fp16 (single pass)
__device__ __half g_wh[(size_t)OUT_F  * IN_F];   // int8 weights, exact in fp16

__device__ int g_w_is_i32;   // weights delivered as int32 words vs packed int8
__device__ int g_sb_swap;    // d_in[2]/d_in[3] order (scales vs bias)

// ---------------------------------------------------------------------------
// Input-interpretation detector (data-driven, deterministic)
// ---------------------------------------------------------------------------
__global__ void detect_kernel(const int* __restrict__ wbuf,
                              const float* __restrict__ maybe_scales) {
    if (threadIdx.x == 0 && blockIdx.x == 0) {
        int ok = 1;
        for (int i = 0; i < 64; i++) {
            int v = wbuf[i];
            if (v < -128 || v > 127) ok = 0;
        }
        g_w_is_i32 = ok;
        int plausible = 1;
        for (int i = 0; i < 64; i++) {
            float s = maybe_scales[i];
            if (!(s > 0.0f && s < 0.5f)) plausible = 0;
        }
        g_sb_swap = plausible ? 0 : 1;
    }
}

// ---------------------------------------------------------------------------
// Conversions: x -> fp16 (u=2^-11 rounding), W -> fp16 (exact, |w|<=127)
// ---------------------------------------------------------------------------
__global__ void convert_x_kernel(const float* __restrict__ x) {
    size_t i = (size_t)blockIdx.x * blockDim.x + threadIdx.x;  // per 4 floats
    float4 v = reinterpret_cast<const float4*>(x)[i];
    __half2* p = reinterpret_cast<__half2*>(g_xh);
    p[2 * i + 0] = __floats2half2_rn(v.x, v.y);
    p[2 * i + 1] = __floats2half2_rn(v.z, v.w);
}

__global__ void convert_w_kernel(const void* __restrict__ w) {
    size_t i = (size_t)blockIdx.x * blockDim.x + threadIdx.x;  // per 4 weights
    float f0, f1, f2, f3;
    if (g_w_is_i32) {
        int4 c = reinterpret_cast<const int4*>(w)[i];
        f0 = (float)c.x; f1 = (float)c.y; f2 = (float)c.z; f3 = (float)c.w;
    } else {
        char4 c = reinterpret_cast<const char4*>(w)[i];
        f0 = (float)c.x; f1 = (float)c.y; f2 = (float)c.z; f3 = (float)c.w;
    }
    __half2* p = reinterpret_cast<__half2*>(g_wh);
    p[2 * i + 0] = __floats2half2_rn(f0, f1);
    p[2 * i + 1] = __floats2half2_rn(f2, f3);
}

// ---------------------------------------------------------------------------
// Single-pass fp16 GEMM: C = X@W^T, epilogue *scales[n] + bias[n].
//   CTA 128x128, BK=64, 3-stage cp.async, 8 warps (4x2), warp tile 32x64,
//   register-level fragment double buffering (ks+1 prefetch under ks MMAs).
// ---------------------------------------------------------------------------
constexpr int BM = 128, BN = 128, BK = 64;
constexpr int STAGES = 3;
constexpr int LDS = BK + 8;                        // 72 elems: conflict-free ldsm
constexpr int STAGE_ELEMS = (BM + BN) * LDS;       // 18432 elems
constexpr int SMEM_BYTES = STAGES * STAGE_ELEMS * 2;  // 110592 B (2 CTAs/SM)

__device__ __forceinline__ uint32_t smem_u32(const void* p) {
    return (uint32_t)__cvta_generic_to_shared(p);
}
__device__ __forceinline__ void cp16(uint32_t dst, const void* src) {
    asm volatile("cp.async.cg.shared.global [%0], [%1], 16;\n" :: "r"(dst), "l"(src));
}
__device__ __forceinline__ void ldsm_x4(uint32_t r[4], uint32_t addr) {
    asm volatile("ldmatrix.sync.aligned.m8n8.x4.shared.b16 {%0,%1,%2,%3}, [%4];\n"
                 : "=r"(r[0]), "=r"(r[1]), "=r"(r[2]), "=r"(r[3]) : "r"(addr));
}
__device__ __forceinline__ void mma16816(float c[4], const uint32_t a[4],
                                         uint32_t b0, uint32_t b1) {
    asm volatile(
        "mma.sync.aligned.m16n8k16.row.col.f32.f16.f16.f32 "
        "{%0,%1,%2,%3}, {%4,%5,%6,%7}, {%8,%9}, {%0,%1,%2,%3};\n"
        : "+f"(c[0]), "+f"(c[1]), "+f"(c[2]), "+f"(c[3])
        : "r"(a[0]), "r"(a[1]), "r"(a[2]), "r"(a[3]), "r"(b0), "r"(b1));
}

__device__ __forceinline__ void load_stage(
    int tid, __half* s, const __half* gA, const __half* gB, int k0) {
    __half* sA = s;
    __half* sB = s + BM * LDS;
#pragma unroll
    for (int i = 0; i < 4; i++) {
        int cid  = tid + i * 256;
        int row  = cid >> 3;          // 0..127
        int col8 = (cid & 7) * 8;     // 8 chunks of 8 halves per 64-elem row
        cp16(smem_u32(sA + row * LDS + col8), gA + (size_t)row * IN_F + k0 + col8);
        cp16(smem_u32(sB + row * LDS + col8), gB + (size_t)row * IN_F + k0 + col8);
    }
}

__global__ __launch_bounds__(256, 2)
void gemm_kernel(const float* __restrict__ p2, const float* __restrict__ p3,
                 float* __restrict__ out) {
    const float* scales = g_sb_swap ? p3 : p2;
    const float* bias   = g_sb_swap ? p2 : p3;

    extern __shared__ __half smem[];
    const int tid = threadIdx.x;
    const int bm0 = blockIdx.y * BM;
    const int bn0 = blockIdx.x * BN;

    const __half* gA = g_xh + (size_t)bm0 * IN_F;
    const __half* gB = g_wh + (size_t)bn0 * IN_F;

    const int w  = tid >> 5, l = tid & 31;
    const int wm = w >> 1,  wn = w & 1;   // 4x2 warp grid; warp tile 32x64

    float acc[2][8][4];
#pragma unroll
    for (int a = 0; a < 2; a++)
#pragma unroll
        for (int b = 0; b < 8; b++)
#pragma unroll
            for (int c = 0; c < 4; c++) acc[a][b][c] = 0.f;

    // ldmatrix per-lane element offsets within a tile
    const int aRow = wm * 32 + (l & 7) + ((l >> 3) & 1) * 8;  // + mt*16
    const int aCol = (l >> 4) * 8;                            // + ks*16
    const int bRow = wn * 64 + (l >> 4) * 8 + (l & 7);        // + q*16
    const int bCol = ((l >> 3) & 1) * 8;                      // + ks*16

    const int KT = IN_F / BK;  // 64

    // Double-buffered register fragments
    uint32_t aF[2][2][4], bF[2][4][4];

#define LOAD_FRAGS(buf, sAu, sBu, ks)                                          \
    do {                                                                       \
        _Pragma("unroll")                                                      \
        for (int q = 0; q < 4; q++)                                            \
            ldsm_x4(bF[buf][q],                                                \
                    (sBu) + ((bRow + q * 16) * LDS + bCol + (ks) * 16) * 2);   \
        _Pragma("unroll")                                                      \
        for (int mt = 0; mt < 2; mt++)                                         \
            ldsm_x4(aF[buf][mt],                                               \
                    (sAu) + ((aRow + mt * 16) * LDS + aCol + (ks) * 16) * 2);  \
    } while (0)

#define MMA_BATCH(buf)                                                         \
    do {                                                                       \
        _Pragma("unroll")                                                      \
        for (int mt = 0; mt < 2; mt++)                                         \
            _Pragma("unroll")                                                  \
            for (int nt = 0; nt < 8; nt++)                                     \
                mma16816(acc[mt][nt], aF[buf][mt],                             \
                         bF[buf][nt >> 1][(nt & 1) * 2],                       \
                         bF[buf][nt >> 1][(nt & 1) * 2 + 1]);                  \
    } while (0)

#pragma unroll
    for (int s = 0; s < STAGES - 1; s++) {
        load_stage(tid, smem + s * STAGE_ELEMS, gA, gB, s * BK);
        asm volatile("cp.async.commit_group;\n" ::: "memory");
    }
    asm volatile("cp.async.wait_group %0;\n" :: "n"(STAGES - 2) : "memory");
    __syncthreads();

    for (int kt = 0; kt < KT; kt++) {
        __half* s = smem + (kt % STAGES) * STAGE_ELEMS;
        const uint32_t sAu = smem_u32(s);
        const uint32_t sBu = smem_u32(s + BM * LDS);

        // Fragments for ks=0, then kick off next-stage global loads so the
        // LSU burst overlaps the MMA body instead of the barrier boundary.
        LOAD_FRAGS(0, sAu, sBu, 0);
        int nkt = kt + STAGES - 1;
        if (nkt < KT)
            load_stage(tid, smem + (nkt % STAGES) * STAGE_ELEMS, gA, gB, nkt * BK);
        asm volatile("cp.async.commit_group;\n" ::: "memory");

#pragma unroll
        for (int ks = 0; ks < 4; ks++) {
            if (ks < 3) LOAD_FRAGS((ks + 1) & 1, sAu, sBu, ks + 1);
            MMA_BATCH(ks & 1);
        }

        asm volatile("cp.async.wait_group %0;\n" :: "n"(STAGES - 2) : "memory");
        __syncthreads();
    }

    // Epilogue: y = acc * scales[n] + bias[n]
    const int mbase = bm0 + wm * 32;
    const int nbase = bn0 + wn * 64;
#pragma unroll
    for (int nt = 0; nt < 8; nt++) {
        int gn = nbase + nt * 8 + (l & 3) * 2;
        float s0 = scales[gn],     s1 = scales[gn + 1];
        float b0 = bias[gn],       b1 = bias[gn + 1];
#pragma unroll
        for (int mt = 0; mt < 2; mt++) {
            int gm = mbase + mt * 16 + (l >> 2);
            float2 v0 = make_float2(fmaf(acc[mt][nt][0], s0, b0),
                                    fmaf(acc[mt][nt][1], s1, b1));
            float2 v1 = make_float2(fmaf(acc[mt][nt][2], s0, b0),
                                    fmaf(acc[mt][nt][3], s1, b1));
            *reinterpret_cast<float2*>(out + (size_t)gm * OUT_F + gn)       = v0;
            *reinterpret_cast<float2*>(out + (size_t)(gm + 8) * OUT_F + gn) = v1;
        }
    }
#undef LOAD_FRAGS
#undef MMA_BATCH
}

// ---------------------------------------------------------------------------
// Launch
// ---------------------------------------------------------------------------
extern "C" void kernel_launch(void* const* d_in, const int* in_sizes, int n_in,
                              void* d_out, int out_size) {
    const float* x   = (const float*)d_in[0];
    const void*  w8  = d_in[1];
    const float* p2  = (const float*)d_in[2];
    const float* p3  = (const float*)d_in[3];
    float*       out = (float*)d_out;

    detect_kernel<<<1, 32>>>((const int*)w8, p2);
    convert_x_kernel<<<((size_t)TOKENS * IN_F) / 4 / 256, 256>>>(x);
    convert_w_kernel<<<((size_t)OUT_F  * IN_F) / 4 / 256, 256>>>(w8);

    cudaFuncSetAttribute(gemm_kernel,
                         cudaFuncAttributeMaxDynamicSharedMemorySize, SMEM_BYTES);
    dim3 grid(OUT_F / BN, TOKENS / BM);   // (32, 64): x fast -> B reuse in L2
    gemm_kernel<<<grid, 256, SMEM_BYTES>>>(p2, p3, out);
}

// round 17
// speedup vs baseline: 5.5651x; 1.0678x over previous
#include <cuda_runtime.h>
#include <cuda_fp16.h>
#include <cstdint>

#define TOKENS 8192
#define IN_F   4096
#define OUT_F  4096

// ---------------------------------------------------------------------------
// Scratch (__device__ globals; alloc-free rule)
// ---------------------------------------------------------------------------
__device__ __half g_xh[(size_t)TOKENS * IN_F];   // x in fp16 (single pass)
__device__ __half g_wh[(size_t)OUT_F  * IN_F];   // int8 weights, exact in fp16

__device__ int g_w_is_i32;   // weights delivered as int32 words vs packed int8
__device__ int g_sb_swap;    // d_in[2]/d_in[3] order (scales vs bias)

// ---------------------------------------------------------------------------
// Input-interpretation detector (data-driven, deterministic)
// ---------------------------------------------------------------------------
__global__ void detect_kernel(const int* __restrict__ wbuf,
                              const float* __restrict__ maybe_scales) {
    if (threadIdx.x == 0 && blockIdx.x == 0) {
        int ok = 1;
        for (int i = 0; i < 64; i++) {
            int v = wbuf[i];
            if (v < -128 || v > 127) ok = 0;
        }
        g_w_is_i32 = ok;
        int plausible = 1;
        for (int i = 0; i < 64; i++) {
            float s = maybe_scales[i];
            if (!(s > 0.0f && s < 0.5f)) plausible = 0;
        }
        g_sb_swap = plausible ? 0 : 1;
    }
}

// ---------------------------------------------------------------------------
// Fused conversion: x -> fp16 (u=2^-11), W -> fp16 (exact, |w|<=127)
//   One launch; blocks [0, NXB) do x, [NXB, NXB+NWB) do W.
// ---------------------------------------------------------------------------
constexpr int NXB = (int)(((size_t)TOKENS * IN_F) / 4 / 256);  // 32768
constexpr int NWB = (int)(((size_t)OUT_F  * IN_F) / 4 / 256);  // 16384

__global__ void convert_all_kernel(const float* __restrict__ x,
                                   const void* __restrict__ w) {
    size_t b = blockIdx.x;
    if (b < (size_t)NXB) {
        size_t i = b * blockDim.x + threadIdx.x;       // per 4 floats
        float4 v = reinterpret_cast<const float4*>(x)[i];
        __half2* p = reinterpret_cast<__half2*>(g_xh);
        p[2 * i + 0] = __floats2half2_rn(v.x, v.y);
        p[2 * i + 1] = __floats2half2_rn(v.z, v.w);
    } else {
        size_t i = (b - NXB) * blockDim.x + threadIdx.x;  // per 4 weights
        float f0, f1, f2, f3;
        if (g_w_is_i32) {
            int4 c = reinterpret_cast<const int4*>(w)[i];
            f0 = (float)c.x; f1 = (float)c.y; f2 = (float)c.z; f3 = (float)c.w;
        } else {
            char4 c = reinterpret_cast<const char4*>(w)[i];
            f0 = (float)c.x; f1 = (float)c.y; f2 = (float)c.z; f3 = (float)c.w;
        }
        __half2* p = reinterpret_cast<__half2*>(g_wh);
        p[2 * i + 0] = __floats2half2_rn(f0, f1);
        p[2 * i + 1] = __floats2half2_rn(f2, f3);
    }
}

// ---------------------------------------------------------------------------
// Single-pass fp16 GEMM: C = X@W^T, epilogue *scales[n] + bias[n].
//   CTA 128x128, BK=64, 3-stage cp.async, 8 warps (4x2), warp tile 32x64.
//   B fragments double-buffered (prefetch ks+1); A single-buffered, loaded
//   after each MMA batch (hidden by tensor-pipe backlog). Regs ~115 < 128.
// ---------------------------------------------------------------------------
constexpr int BM = 128, BN = 128, BK = 64;
constexpr int STAGES = 3;
constexpr int LDS = BK + 8;                        // 72 elems: conflict-free ldsm
constexpr int STAGE_ELEMS = (BM + BN) * LDS;       // 18432 elems
constexpr int SMEM_BYTES = STAGES * STAGE_ELEMS * 2;  // 110592 B (2 CTAs/SM)

__device__ __forceinline__ uint32_t smem_u32(const void* p) {
    return (uint32_t)__cvta_generic_to_shared(p);
}
__device__ __forceinline__ void cp16(uint32_t dst, const void* src) {
    asm volatile("cp.async.cg.shared.global [%0], [%1], 16;\n" :: "r"(dst), "l"(src));
}
__device__ __forceinline__ void ldsm_x4(uint32_t r[4], uint32_t addr) {
    asm volatile("ldmatrix.sync.aligned.m8n8.x4.shared.b16 {%0,%1,%2,%3}, [%4];\n"
                 : "=r"(r[0]), "=r"(r[1]), "=r"(r[2]), "=r"(r[3]) : "r"(addr));
}
__device__ __forceinline__ void mma16816(float c[4], const uint32_t a[4],
                                         uint32_t b0, uint32_t b1) {
    asm volatile(
        "mma.sync.aligned.m16n8k16.row.col.f32.f16.f16.f32 "
        "{%0,%1,%2,%3}, {%4,%5,%6,%7}, {%8,%9}, {%0,%1,%2,%3};\n"
        : "+f"(c[0]), "+f"(c[1]), "+f"(c[2]), "+f"(c[3])
        : "r"(a[0]), "r"(a[1]), "r"(a[2]), "r"(a[3]), "r"(b0), "r"(b1));
}

__device__ __forceinline__ void load_stage(
    int tid, __half* s, const __half* gA, const __half* gB, int k0) {
    __half* sA = s;
    __half* sB = s + BM * LDS;
#pragma unroll
    for (int i = 0; i < 4; i++) {
        int cid  = tid + i * 256;
        int row  = cid >> 3;          // 0..127
        int col8 = (cid & 7) * 8;     // 8 chunks of 8 halves per 64-elem row
        cp16(smem_u32(sA + row * LDS + col8), gA + (size_t)row * IN_F + k0 + col8);
        cp16(smem_u32(sB + row * LDS + col8), gB + (size_t)row * IN_F + k0 + col8);
    }
}

__global__ __launch_bounds__(256, 2)
void gemm_kernel(const float* __restrict__ p2, const float* __restrict__ p3,
                 float* __restrict__ out) {
    const float* scales = g_sb_swap ? p3 : p2;
    const float* bias   = g_sb_swap ? p2 : p3;

    extern __shared__ __half smem[];
    const int tid = threadIdx.x;
    const int bm0 = blockIdx.y * BM;
    const int bn0 = blockIdx.x * BN;

    const __half* gA = g_xh + (size_t)bm0 * IN_F;
    const __half* gB = g_wh + (size_t)bn0 * IN_F;

    const int w  = tid >> 5, l = tid & 31;
    const int wm = w >> 1,  wn = w & 1;   // 4x2 warp grid; warp tile 32x64

    float acc[2][8][4];
#pragma unroll
    for (int a = 0; a < 2; a++)
#pragma unroll
        for (int b = 0; b < 8; b++)
#pragma unroll
            for (int c = 0; c < 4; c++) acc[a][b][c] = 0.f;

    // Precomputed LDSM byte offsets within a stage (loop-invariant)
    const int aRow = wm * 32 + (l & 7) + ((l >> 3) & 1) * 8;
    const int aCol = (l >> 4) * 8;
    const int bRow = wn * 64 + (l >> 4) * 8 + (l & 7);
    const int bCol = ((l >> 3) & 1) * 8;
    uint32_t aOff[2], bOff[4];
#pragma unroll
    for (int mt = 0; mt < 2; mt++)
        aOff[mt] = ((aRow + mt * 16) * LDS + aCol) * 2;
#pragma unroll
    for (int q = 0; q < 4; q++)
        bOff[q] = ((bRow + q * 16) * LDS + bCol + BM * LDS) * 2;  // B region

    const int KT = IN_F / BK;  // 64

    uint32_t aF[2][4], bF[2][4][4];

#define LOAD_B(buf, sU, ks)                                                    \
    do {                                                                       \
        _Pragma("unroll")                                                      \
        for (int q = 0; q < 4; q++)                                            \
            ldsm_x4(bF[buf][q], (sU) + bOff[q] + (ks) * 32);                   \
    } while (0)

#define LOAD_A(sU, ks)                                                         \
    do {                                                                       \
        _Pragma("unroll")                                                      \
        for (int mt = 0; mt < 2; mt++)                                         \
            ldsm_x4(aF[mt], (sU) + aOff[mt] + (ks) * 32);                      \
    } while (0)

#define MMA_BATCH(buf)                                                         \
    do {                                                                       \
        _Pragma("unroll")                                                      \
        for (int mt = 0; mt < 2; mt++)                                         \
            _Pragma("unroll")                                                  \
            for (int nt = 0; nt < 8; nt++)                                     \
                mma16816(acc[mt][nt], aF[mt],                                  \
                         bF[buf][nt >> 1][(nt & 1) * 2],                       \
                         bF[buf][nt >> 1][(nt & 1) * 2 + 1]);                  \
    } while (0)

#pragma unroll
    for (int s = 0; s < STAGES - 1; s++) {
        load_stage(tid, smem + s * STAGE_ELEMS, gA, gB, s * BK);
        asm volatile("cp.async.commit_group;\n" ::: "memory");
    }
    asm volatile("cp.async.wait_group %0;\n" :: "n"(STAGES - 2) : "memory");
    __syncthreads();

    for (int kt = 0; kt < KT; kt++) {
        const uint32_t sU = smem_u32(smem + (kt % STAGES) * STAGE_ELEMS);

        // First fragments of this stage, then kick off next-stage globals so
        // the LDGSTS issue burst covers the LDSM latency before batch 0.
        LOAD_B(0, sU, 0);
        LOAD_A(sU, 0);
        int nkt = kt + STAGES - 1;
        if (nkt < KT)
            load_stage(tid, smem + (nkt % STAGES) * STAGE_ELEMS, gA, gB, nkt * BK);
        asm volatile("cp.async.commit_group;\n" ::: "memory");

#pragma unroll
        for (int ks = 0; ks < 4; ks++) {
            if (ks < 3) LOAD_B((ks + 1) & 1, sU, ks + 1);  // prefetch B
            MMA_BATCH(ks & 1);                             // consume aF + bF[ks]
            if (ks < 3) LOAD_A(sU, ks + 1);                // reload A after use
        }

        asm volatile("cp.async.wait_group %0;\n" :: "n"(STAGES - 2) : "memory");
        __syncthreads();
    }

    // Epilogue: y = acc * scales[n] + bias[n]
    const int mbase = bm0 + wm * 32;
    const int nbase = bn0 + wn * 64;
#pragma unroll
    for (int nt = 0; nt < 8; nt++) {
        int gn = nbase + nt * 8 + (l & 3) * 2;
        float s0 = scales[gn],     s1 = scales[gn + 1];
        float b0 = bias[gn],       b1 = bias[gn + 1];
#pragma unroll
        for (int mt = 0; mt < 2; mt++) {
            int gm = mbase + mt * 16 + (l >> 2);
            float2 v0 = make_float2(fmaf(acc[mt][nt][0], s0, b0),
                                    fmaf(acc[mt][nt][1], s1, b1));
            float2 v1 = make_float2(fmaf(acc[mt][nt][2], s0, b0),
                                    fmaf(acc[mt][nt][3], s1, b1));
            *reinterpret_cast<float2*>(out + (size_t)gm * OUT_F + gn)       = v0;
            *reinterpret_cast<float2*>(out + (size_t)(gm + 8) * OUT_F + gn) = v1;
        }
    }
#undef LOAD_B
#undef LOAD_A
#undef MMA_BATCH
}

// ---------------------------------------------------------------------------
// Launch
// ---------------------------------------------------------------------------
extern "C" void kernel_launch(void* const* d_in, const int* in_sizes, int n_in,
                              void* d_out, int out_size) {
    const float* x   = (const float*)d_in[0];
    const void*  w8  = d_in[1];
    const float* p2  = (const float*)d_in[2];
    const float* p3  = (const float*)d_in[3];
    float*       out = (float*)d_out;

    detect_kernel<<<1, 32>>>((const int*)w8, p2);
    convert_all_kernel<<<NXB + NWB, 256>>>(x, w8);

    cudaFuncSetAttribute(gemm_kernel,
                         cudaFuncAttributeMaxDynamicSharedMemorySize, SMEM_BYTES);
    dim3 grid(OUT_F / BN, TOKENS / BM);   // (32, 64): x fast -> B reuse in L2
    gemm_kernel<<<grid, 256, SMEM_BYTES>>>(p2, p3, out);
}